// round 4
// baseline (speedup 1.0000x reference)
#include <cuda_runtime.h>

#define TSEQ  2048
#define CDIM  1024
#define NB    2
#define NHEAD 16
#define DHDIM 64
#define BTROWS (NB * TSEQ)   // 4096

// Scratch for Q, K, V projections (flat (B*T, C) row-major == (B,H,T,Dh) view)
__device__ float g_q[NB * TSEQ * CDIM];
__device__ float g_k[NB * TSEQ * CDIM];
__device__ float g_v[NB * TSEQ * CDIM];

// ---------------------------------------------------------------------------
// QKV projection: dst[m,n] = sum_k X[m,k] * W[n,k]   (x @ W^T)
// 128x128 tile, BK=8, 256 threads, 8x8 microtile, double-buffered smem.
// ---------------------------------------------------------------------------
__global__ __launch_bounds__(256, 2)
void qkv_gemm_kernel(const float* __restrict__ X,
                     const float* __restrict__ Wq,
                     const float* __restrict__ Wk,
                     const float* __restrict__ Wv) {
    __shared__ float As[2][8][128];
    __shared__ float Bs[2][8][128];

    const float* __restrict__ W =
        (blockIdx.z == 0) ? Wq : (blockIdx.z == 1) ? Wk : Wv;
    float* __restrict__ dst =
        (blockIdx.z == 0) ? g_q : (blockIdx.z == 1) ? g_k : g_v;

    const int m0  = blockIdx.x * 128;
    const int n0  = blockIdx.y * 128;
    const int tid = threadIdx.x;
    const int tx  = tid & 15;
    const int ty  = tid >> 4;
    const int lm  = tid >> 1;          // 0..127
    const int lk  = (tid & 1) << 2;    // 0 or 4

    const float* aPtr = X + (size_t)(m0 + lm) * CDIM + lk;
    const float* bPtr = W + (size_t)(n0 + lm) * CDIM + lk;

    float4 aReg = *(const float4*)aPtr;
    float4 bReg = *(const float4*)bPtr;
    As[0][lk + 0][lm] = aReg.x; As[0][lk + 1][lm] = aReg.y;
    As[0][lk + 2][lm] = aReg.z; As[0][lk + 3][lm] = aReg.w;
    Bs[0][lk + 0][lm] = bReg.x; Bs[0][lk + 1][lm] = bReg.y;
    Bs[0][lk + 2][lm] = bReg.z; Bs[0][lk + 3][lm] = bReg.w;
    __syncthreads();

    float acc[8][8];
    #pragma unroll
    for (int i = 0; i < 8; i++)
        #pragma unroll
        for (int j = 0; j < 8; j++) acc[i][j] = 0.0f;

    int buf = 0;
    for (int k0 = 8; k0 <= CDIM; k0 += 8) {
        const bool more = (k0 < CDIM);
        if (more) {
            aReg = *(const float4*)(aPtr + k0);
            bReg = *(const float4*)(bPtr + k0);
        }
        #pragma unroll
        for (int kk = 0; kk < 8; kk++) {
            float a[8], b[8];
            *(float4*)(a)     = *(const float4*)&As[buf][kk][ty * 4];
            *(float4*)(a + 4) = *(const float4*)&As[buf][kk][64 + ty * 4];
            *(float4*)(b)     = *(const float4*)&Bs[buf][kk][tx * 4];
            *(float4*)(b + 4) = *(const float4*)&Bs[buf][kk][64 + tx * 4];
            #pragma unroll
            for (int i = 0; i < 8; i++)
                #pragma unroll
                for (int j = 0; j < 8; j++)
                    acc[i][j] += a[i] * b[j];
        }
        if (more) {
            buf ^= 1;
            As[buf][lk + 0][lm] = aReg.x; As[buf][lk + 1][lm] = aReg.y;
            As[buf][lk + 2][lm] = aReg.z; As[buf][lk + 3][lm] = aReg.w;
            Bs[buf][lk + 0][lm] = bReg.x; Bs[buf][lk + 1][lm] = bReg.y;
            Bs[buf][lk + 2][lm] = bReg.z; Bs[buf][lk + 3][lm] = bReg.w;
            __syncthreads();
        }
    }

    #pragma unroll
    for (int i = 0; i < 8; i++) {
        int r = m0 + ((i & 4) ? 64 : 0) + ty * 4 + (i & 3);
        float* o = dst + (size_t)r * CDIM + n0;
        *(float4*)(o + tx * 4) =
            make_float4(acc[i][0], acc[i][1], acc[i][2], acc[i][3]);
        *(float4*)(o + 64 + tx * 4) =
            make_float4(acc[i][4], acc[i][5], acc[i][6], acc[i][7]);
    }
}

// ---------------------------------------------------------------------------
// Causal flash attention, fp32. One block = 64 query rows of one (b,h) pair.
// 256 threads (16x16), 4x4 microtile. Online softmax with 16-lane shuffles.
// Smem: QsT (transposed Q), KP (K swizzled / reused for P), Vs. 48 KB exact.
// ---------------------------------------------------------------------------
__device__ __forceinline__ int ksw(int c) {
    // per-row xor swizzle for conflict-free column access of the K tile
    return (c & 31) ^ ((c & 32) >> 5);
}

__global__ __launch_bounds__(256)
void attn_kernel(float* __restrict__ out) {
    __shared__ float QsT[64][64];   // [d][r]
    __shared__ float KP[64 * 64];   // K: [c][d ^ ksw(c)] ; later P: [r][c]
    __shared__ float Vs[64][64];    // [c][d]

    const int qi = blockIdx.x;            // query tile 0..31
    const int bh = blockIdx.y;            // (b*H + h) 0..31
    const size_t base = (size_t)bh * TSEQ * DHDIM;
    const float* Qh = g_q + base + (size_t)qi * 64 * DHDIM;
    const float* Kh = g_k + base;
    const float* Vh = g_v + base;
    float* Oh = out + base + (size_t)qi * 64 * DHDIM;

    const int tid = threadIdx.x;
    const int tx  = tid & 15;
    const int ty  = tid >> 4;

    // Load Q tile, store transposed [d][r]
    #pragma unroll
    for (int it = 0; it < 4; it++) {
        int lin = it * 1024 + tid * 4;
        float4 qv = *(const float4*)(Qh + lin);
        int r = lin >> 6, c = lin & 63;
        QsT[c + 0][r] = qv.x; QsT[c + 1][r] = qv.y;
        QsT[c + 2][r] = qv.z; QsT[c + 3][r] = qv.w;
    }

    float acc[4][4];
    float mrow[4], lrow[4];
    #pragma unroll
    for (int i = 0; i < 4; i++) {
        mrow[i] = -1e30f; lrow[i] = 0.0f;
        #pragma unroll
        for (int jj = 0; jj < 4; jj++) acc[i][jj] = 0.0f;
    }

    int cidx[4], cbase[4], csw[4];
    #pragma unroll
    for (int jj = 0; jj < 4; jj++) {
        int c = tx * 4 + jj;
        cidx[jj]  = c;
        cbase[jj] = c * 64;
        csw[jj]   = ksw(c);
    }

    const float SCALE_LOG2E = 0.125f * 1.4426950408889634f; // 1/sqrt(64)*log2(e)

    for (int j = 0; j <= qi; j++) {
        __syncthreads();   // previous tile's KP/Vs readers done (also covers QsT init)
        #pragma unroll
        for (int it = 0; it < 4; it++) {
            int lin = it * 1024 + tid * 4;
            int r = lin >> 6, c = lin & 63;
            float4 kv = *(const float4*)(Kh + (size_t)j * 64 * DHDIM + lin);
            int sw = ksw(r);
            KP[r * 64 + ((c + 0) ^ sw)] = kv.x;
            KP[r * 64 + ((c + 1) ^ sw)] = kv.y;
            KP[r * 64 + ((c + 2) ^ sw)] = kv.z;
            KP[r * 64 + ((c + 3) ^ sw)] = kv.w;
            *(float4*)&Vs[r][c] = *(const float4*)(Vh + (size_t)j * 64 * DHDIM + lin);
        }
        __syncthreads();

        // S = Q @ K^T  (rank-1 updates over d)
        float s[4][4];
        #pragma unroll
        for (int i = 0; i < 4; i++)
            #pragma unroll
            for (int jj = 0; jj < 4; jj++) s[i][jj] = 0.0f;

        #pragma unroll
        for (int d = 0; d < 64; d++) {
            float4 a4 = *(const float4*)&QsT[d][ty * 4];
            #pragma unroll
            for (int jj = 0; jj < 4; jj++) {
                float b = KP[cbase[jj] + (d ^ csw[jj])];
                s[0][jj] += a4.x * b;
                s[1][jj] += a4.y * b;
                s[2][jj] += a4.z * b;
                s[3][jj] += a4.w * b;
            }
        }

        const bool diag = (j == qi);
        #pragma unroll
        for (int i = 0; i < 4; i++) {
            int r = ty * 4 + i;
            #pragma unroll
            for (int jj = 0; jj < 4; jj++) {
                float val = s[i][jj] * SCALE_LOG2E;
                if (diag && cidx[jj] > r) val = -1e30f;
                s[i][jj] = val;
            }
        }

        // online softmax (row groups = 16 consecutive lanes)
        #pragma unroll
        for (int i = 0; i < 4; i++) {
            float mloc = fmaxf(fmaxf(s[i][0], s[i][1]), fmaxf(s[i][2], s[i][3]));
            #pragma unroll
            for (int off = 8; off >= 1; off >>= 1)
                mloc = fmaxf(mloc, __shfl_xor_sync(0xffffffffu, mloc, off));
            float mnew  = fmaxf(mrow[i], mloc);
            float alpha = exp2f(mrow[i] - mnew);
            mrow[i] = mnew;
            float rs = 0.0f;
            #pragma unroll
            for (int jj = 0; jj < 4; jj++) {
                float p = exp2f(s[i][jj] - mnew);
                s[i][jj] = p;
                rs += p;
            }
            #pragma unroll
            for (int off = 8; off >= 1; off >>= 1)
                rs += __shfl_xor_sync(0xffffffffu, rs, off);
            lrow[i] = lrow[i] * alpha + rs;
            #pragma unroll
            for (int jj = 0; jj < 4; jj++) acc[i][jj] *= alpha;
        }

        __syncthreads();   // all K reads done before P overwrites KP
        #pragma unroll
        for (int i = 0; i < 4; i++)
            *(float4*)&KP[(ty * 4 + i) * 64 + tx * 4] =
                make_float4(s[i][0], s[i][1], s[i][2], s[i][3]);
        __syncthreads();

        // O += P @ V  (rank-1 updates over key index c)
        #pragma unroll
        for (int c = 0; c < 64; c++) {
            float a0 = KP[(ty * 4 + 0) * 64 + c];
            float a1 = KP[(ty * 4 + 1) * 64 + c];
            float a2 = KP[(ty * 4 + 2) * 64 + c];
            float a3 = KP[(ty * 4 + 3) * 64 + c];
            float4 b = *(const float4*)&Vs[c][tx * 4];
            acc[0][0] += a0 * b.x; acc[0][1] += a0 * b.y; acc[0][2] += a0 * b.z; acc[0][3] += a0 * b.w;
            acc[1][0] += a1 * b.x; acc[1][1] += a1 * b.y; acc[1][2] += a1 * b.z; acc[1][3] += a1 * b.w;
            acc[2][0] += a2 * b.x; acc[2][1] += a2 * b.y; acc[2][2] += a2 * b.z; acc[2][3] += a2 * b.w;
            acc[3][0] += a3 * b.x; acc[3][1] += a3 * b.y; acc[3][2] += a3 * b.z; acc[3][3] += a3 * b.w;
        }
    }

    #pragma unroll
    for (int i = 0; i < 4; i++) {
        float inv = 1.0f / lrow[i];
        *(float4*)(Oh + (ty * 4 + i) * DHDIM + tx * 4) =
            make_float4(acc[i][0] * inv, acc[i][1] * inv,
                        acc[i][2] * inv, acc[i][3] * inv);
    }
}

// ---------------------------------------------------------------------------
extern "C" void kernel_launch(void* const* d_in, const int* in_sizes, int n_in,
                              void* d_out, int out_size) {
    const float* x  = (const float*)d_in[0];
    const float* Wq = (const float*)d_in[1];
    const float* Wk = (const float*)d_in[2];
    const float* Wv = (const float*)d_in[3];
    float* out = (float*)d_out;

    dim3 ggrid(BTROWS / 128, CDIM / 128, 3);   // 32 x 8 x 3
    qkv_gemm_kernel<<<ggrid, 256>>>(x, Wq, Wk, Wv);

    dim3 agrid(TSEQ / 64, NB * NHEAD);         // 32 x 32
    attn_kernel<<<agrid, 256>>>(out);

    (void)in_sizes; (void)n_in; (void)out_size;
}

// round 7
// speedup vs baseline: 1.6425x; 1.6425x over previous
#include <cuda_runtime.h>

#define TSEQ  2048
#define CDIM  1024
#define NB    2
#define NHEAD 16
#define DHDIM 64
#define BTROWS (NB * TSEQ)   // 4096

typedef unsigned long long ull;

// Scratch for Q, K, V projections (flat (B*T, C) row-major == (B,H,T,Dh) view)
__device__ float g_q[NB * TSEQ * CDIM];
__device__ float g_k[NB * TSEQ * CDIM];
__device__ float g_v[NB * TSEQ * CDIM];

// ---------------- packed fp32x2 helpers (SASS FFMA2 path) -------------------
__device__ __forceinline__ ull bcast2(float x) {
    ull r; asm("mov.b64 %0, {%1, %1};" : "=l"(r) : "f"(x)); return r;
}
__device__ __forceinline__ ull pack2(float lo, float hi) {
    ull r; asm("mov.b64 %0, {%1, %2};" : "=l"(r) : "f"(lo), "f"(hi)); return r;
}
__device__ __forceinline__ float2 unpack2(ull v) {
    float2 r; asm("mov.b64 {%0, %1}, %2;" : "=f"(r.x), "=f"(r.y) : "l"(v)); return r;
}
__device__ __forceinline__ void ffma2(ull& d, ull a, ull b) {
    asm("fma.rn.f32x2 %0, %1, %2, %0;" : "+l"(d) : "l"(a), "l"(b));
}
__device__ __forceinline__ void fmul2(ull& d, ull a) {
    asm("mul.rn.f32x2 %0, %0, %1;" : "+l"(d) : "l"(a));
}

// ---------------------------------------------------------------------------
// QKV projection: dst[m,n] = sum_k X[m,k] * W[n,k]   (x @ W^T)
// 128x128 tile, BK=8, 256 threads, 8x8 microtile (packed f32x2 pairs along n),
// double-buffered smem.
// ---------------------------------------------------------------------------
__global__ __launch_bounds__(256, 2)
void qkv_gemm_kernel(const float* __restrict__ X,
                     const float* __restrict__ Wq,
                     const float* __restrict__ Wk,
                     const float* __restrict__ Wv) {
    __shared__ float As[2][8][128];
    __shared__ float Bs[2][8][128];

    const float* __restrict__ W =
        (blockIdx.z == 0) ? Wq : (blockIdx.z == 1) ? Wk : Wv;
    float* __restrict__ dst =
        (blockIdx.z == 0) ? g_q : (blockIdx.z == 1) ? g_k : g_v;

    const int m0  = blockIdx.x * 128;
    const int n0  = blockIdx.y * 128;
    const int tid = threadIdx.x;
    const int tx  = tid & 15;
    const int ty  = tid >> 4;
    const int lm  = tid >> 1;          // 0..127
    const int lk  = (tid & 1) << 2;    // 0 or 4

    const float* aPtr = X + (size_t)(m0 + lm) * CDIM + lk;
    const float* bPtr = W + (size_t)(n0 + lm) * CDIM + lk;

    float4 aReg = *(const float4*)aPtr;
    float4 bReg = *(const float4*)bPtr;
    As[0][lk + 0][lm] = aReg.x; As[0][lk + 1][lm] = aReg.y;
    As[0][lk + 2][lm] = aReg.z; As[0][lk + 3][lm] = aReg.w;
    Bs[0][lk + 0][lm] = bReg.x; Bs[0][lk + 1][lm] = bReg.y;
    Bs[0][lk + 2][lm] = bReg.z; Bs[0][lk + 3][lm] = bReg.w;
    __syncthreads();

    ull acc2[8][4];
    #pragma unroll
    for (int i = 0; i < 8; i++)
        #pragma unroll
        for (int j = 0; j < 4; j++) acc2[i][j] = 0ull;

    int buf = 0;
    for (int k0 = 8; k0 <= CDIM; k0 += 8) {
        const bool more = (k0 < CDIM);
        if (more) {
            aReg = *(const float4*)(aPtr + k0);
            bReg = *(const float4*)(bPtr + k0);
        }
        #pragma unroll
        for (int kk = 0; kk < 8; kk++) {
            float4 av0 = *(const float4*)&As[buf][kk][ty * 4];
            float4 av1 = *(const float4*)&As[buf][kk][64 + ty * 4];
            longlong2 bv0 = *(const longlong2*)&Bs[buf][kk][tx * 4];
            longlong2 bv1 = *(const longlong2*)&Bs[buf][kk][64 + tx * 4];
            ull bp0 = (ull)bv0.x, bp1 = (ull)bv0.y;
            ull bp2 = (ull)bv1.x, bp3 = (ull)bv1.y;
            float a[8] = {av0.x, av0.y, av0.z, av0.w,
                          av1.x, av1.y, av1.z, av1.w};
            #pragma unroll
            for (int i = 0; i < 8; i++) {
                ull a2 = bcast2(a[i]);
                ffma2(acc2[i][0], a2, bp0);
                ffma2(acc2[i][1], a2, bp1);
                ffma2(acc2[i][2], a2, bp2);
                ffma2(acc2[i][3], a2, bp3);
            }
        }
        if (more) {
            buf ^= 1;
            As[buf][lk + 0][lm] = aReg.x; As[buf][lk + 1][lm] = aReg.y;
            As[buf][lk + 2][lm] = aReg.z; As[buf][lk + 3][lm] = aReg.w;
            Bs[buf][lk + 0][lm] = bReg.x; Bs[buf][lk + 1][lm] = bReg.y;
            Bs[buf][lk + 2][lm] = bReg.z; Bs[buf][lk + 3][lm] = bReg.w;
            __syncthreads();
        }
    }

    #pragma unroll
    for (int i = 0; i < 8; i++) {
        int r = m0 + ((i & 4) ? 64 : 0) + ty * 4 + (i & 3);
        float* o = dst + (size_t)r * CDIM + n0;
        float2 c0 = unpack2(acc2[i][0]);
        float2 c1 = unpack2(acc2[i][1]);
        float2 c2 = unpack2(acc2[i][2]);
        float2 c3 = unpack2(acc2[i][3]);
        *(float4*)(o + tx * 4)      = make_float4(c0.x, c0.y, c1.x, c1.y);
        *(float4*)(o + 64 + tx * 4) = make_float4(c2.x, c2.y, c3.x, c3.y);
    }
}

// ---------------------------------------------------------------------------
// Causal flash attention, fp32, packed f32x2.
// Block = 64 query rows x one (b,h); key tiles of 128.
// 256 threads as (tx 0..15, ty 0..15).
//   S tile:  rows r = ty+16i (i<4), cols c = tx+16jj (jj<8), packed pairs
//            (tx+32p, tx+32p+16). Dot-product form, natural [t][d] layouts.
//   O tile:  rows r = ty+16i, dh cols {2tx,2tx+1,2tx+32,2tx+33} (f32x2 pairs).
// Smem (dynamic, 87040 B): Qs[64][68] | KsP: K[128][68] reused as P[64][128]
//                          | Vs[128][68].  2 CTAs/SM.
// ---------------------------------------------------------------------------
#define SQ 68
#define ATTN_SMEM_FLOATS (64 * SQ + 128 * SQ + 128 * SQ)

__global__ __launch_bounds__(256, 2)
void attn_kernel(float* __restrict__ out) {
    extern __shared__ float sm[];
    float* __restrict__ Qs  = sm;                    // [64][68]
    float* __restrict__ KsP = sm + 64 * SQ;          // K [128][68] / P [64][128]
    float* __restrict__ Vs  = KsP + 128 * SQ;        // [128][68]

    const int qi = (int)gridDim.x - 1 - (int)blockIdx.x;  // heavy tiles first
    const int bh = blockIdx.y;
    const int q0 = qi * 64;
    const size_t base = (size_t)bh * (TSEQ * DHDIM);
    const float* __restrict__ Qg = g_q + base + (size_t)q0 * DHDIM;
    const float* __restrict__ Kg = g_k + base;
    const float* __restrict__ Vg = g_v + base;
    float* __restrict__ Og = out + base + (size_t)q0 * DHDIM;

    const int tid = threadIdx.x;
    const int tx  = tid & 15;
    const int ty  = tid >> 4;

    // Load Q tile (64x64), natural layout, padded stride
    #pragma unroll
    for (int it = 0; it < 4; it++) {
        int lin = it * 1024 + tid * 4;
        int r = lin >> 6, c = lin & 63;
        *(float4*)&Qs[r * SQ + c] = *(const float4*)(Qg + lin);
    }

    ull oacc[4][2];
    float mrow[4], lrow[4];
    #pragma unroll
    for (int i = 0; i < 4; i++) {
        oacc[i][0] = 0ull; oacc[i][1] = 0ull;
        mrow[i] = -1e30f;  lrow[i] = 0.0f;
    }

    const float SCL = 0.125f * 1.4426950408889634f;  // 1/sqrt(64) * log2(e)
    const int nt = (q0 + 63) / 128 + 1;

    for (int j = 0; j < nt; j++) {
        __syncthreads();   // prior PV readers of KsP/Vs done (covers Qs on j=0)
        {
            const float* Kt = Kg + (size_t)j * 128 * DHDIM;
            const float* Vt = Vg + (size_t)j * 128 * DHDIM;
            #pragma unroll
            for (int it = 0; it < 8; it++) {
                int lin = it * 1024 + tid * 4;
                int r = lin >> 6, c = lin & 63;
                *(float4*)&KsP[r * SQ + c] = *(const float4*)(Kt + lin);
                *(float4*)&Vs[r * SQ + c]  = *(const float4*)(Vt + lin);
            }
        }
        __syncthreads();

        // ---- S = Q @ K^T, packed pairs over column-halves ----
        ull s2[4][4];
        #pragma unroll
        for (int i = 0; i < 4; i++)
            #pragma unroll
            for (int p = 0; p < 4; p++) s2[i][p] = 0ull;

        #pragma unroll 2
        for (int d4 = 0; d4 < DHDIM; d4 += 4) {
            float4 q4[4], ka[4], kb[4];
            #pragma unroll
            for (int i = 0; i < 4; i++)
                q4[i] = *(const float4*)&Qs[(ty + 16 * i) * SQ + d4];
            #pragma unroll
            for (int p = 0; p < 4; p++) {
                ka[p] = *(const float4*)&KsP[(tx + 32 * p) * SQ + d4];
                kb[p] = *(const float4*)&KsP[(tx + 32 * p + 16) * SQ + d4];
            }
            #pragma unroll
            for (int e = 0; e < 4; e++) {
                ull bp[4];
                #pragma unroll
                for (int p = 0; p < 4; p++)
                    bp[p] = pack2(((const float*)&ka[p])[e],
                                  ((const float*)&kb[p])[e]);
                #pragma unroll
                for (int i = 0; i < 4; i++) {
                    ull a2 = bcast2(((const float*)&q4[i])[e]);
                    ffma2(s2[i][0], a2, bp[0]);
                    ffma2(s2[i][1], a2, bp[1]);
                    ffma2(s2[i][2], a2, bp[2]);
                    ffma2(s2[i][3], a2, bp[3]);
                }
            }
        }

        // ---- unpack, scale, causal mask ----
        float s[4][8];
        #pragma unroll
        for (int i = 0; i < 4; i++)
            #pragma unroll
            for (int p = 0; p < 4; p++) {
                float2 u = unpack2(s2[i][p]);
                s[i][2 * p]     = u.x;
                s[i][2 * p + 1] = u.y;
            }

        const bool full = (j * 128 + 127 <= q0);
        #pragma unroll
        for (int i = 0; i < 4; i++) {
            int rg = q0 + ty + 16 * i;
            #pragma unroll
            for (int jj = 0; jj < 8; jj++) {
                float v = s[i][jj] * SCL;
                if (!full) {
                    int c = j * 128 + tx + 16 * jj;
                    if (c > rg) v = -1e30f;
                }
                s[i][jj] = v;
            }
        }

        // ---- online softmax (rows shared by 16 consecutive lanes) ----
        #pragma unroll
        for (int i = 0; i < 4; i++) {
            float mloc = fmaxf(fmaxf(fmaxf(s[i][0], s[i][1]), fmaxf(s[i][2], s[i][3])),
                               fmaxf(fmaxf(s[i][4], s[i][5]), fmaxf(s[i][6], s[i][7])));
            #pragma unroll
            for (int off = 8; off >= 1; off >>= 1)
                mloc = fmaxf(mloc, __shfl_xor_sync(0xffffffffu, mloc, off));
            float mnew  = fmaxf(mrow[i], mloc);
            float alpha = exp2f(mrow[i] - mnew);
            mrow[i] = mnew;
            float rs = 0.0f;
            #pragma unroll
            for (int jj = 0; jj < 8; jj++) {
                float p = exp2f(s[i][jj] - mnew);
                s[i][jj] = p;
                rs += p;
            }
            #pragma unroll
            for (int off = 8; off >= 1; off >>= 1)
                rs += __shfl_xor_sync(0xffffffffu, rs, off);
            lrow[i] = lrow[i] * alpha + rs;
            ull al2 = bcast2(alpha);
            fmul2(oacc[i][0], al2);
            fmul2(oacc[i][1], al2);
        }

        __syncthreads();   // all K reads done before P overwrites KsP
        #pragma unroll
        for (int i = 0; i < 4; i++)
            #pragma unroll
            for (int jj = 0; jj < 8; jj++)
                KsP[(ty + 16 * i) * 128 + tx + 16 * jj] = s[i][jj];
        __syncthreads();

        // ---- O += P @ V  (v pairs contiguous in dh; p broadcast-packed) ----
        #pragma unroll 4
        for (int c = 0; c < 128; c++) {
            ull v0 = *(const ull*)&Vs[c * SQ + 2 * tx];
            ull v1 = *(const ull*)&Vs[c * SQ + 2 * tx + 32];
            #pragma unroll
            for (int i = 0; i < 4; i++) {
                ull p2 = bcast2(KsP[(ty + 16 * i) * 128 + c]);
                ffma2(oacc[i][0], p2, v0);
                ffma2(oacc[i][1], p2, v1);
            }
        }
    }

    #pragma unroll
    for (int i = 0; i < 4; i++) {
        float inv = 1.0f / lrow[i];
        float2 u0 = unpack2(oacc[i][0]);
        float2 u1 = unpack2(oacc[i][1]);
        int r = ty + 16 * i;
        *(float2*)&Og[r * DHDIM + 2 * tx]      = make_float2(u0.x * inv, u0.y * inv);
        *(float2*)&Og[r * DHDIM + 2 * tx + 32] = make_float2(u1.x * inv, u1.y * inv);
    }
}

// ---------------------------------------------------------------------------
extern "C" void kernel_launch(void* const* d_in, const int* in_sizes, int n_in,
                              void* d_out, int out_size) {
    const float* x  = (const float*)d_in[0];
    const float* Wq = (const float*)d_in[1];
    const float* Wk = (const float*)d_in[2];
    const float* Wv = (const float*)d_in[3];
    float* out = (float*)d_out;

    static bool attr_done = false;
    if (!attr_done) {
        cudaFuncSetAttribute(attn_kernel,
                             cudaFuncAttributeMaxDynamicSharedMemorySize,
                             ATTN_SMEM_FLOATS * (int)sizeof(float));
        attr_done = true;
    }

    dim3 ggrid(BTROWS / 128, CDIM / 128, 3);   // 32 x 8 x 3
    qkv_gemm_kernel<<<ggrid, 256>>>(x, Wq, Wk, Wv);

    dim3 agrid(TSEQ / 64, NB * NHEAD);         // 32 x 32
    attn_kernel<<<agrid, 256, ATTN_SMEM_FLOATS * (int)sizeof(float)>>>(out);

    (void)in_sizes; (void)n_in; (void)out_size;
}

// round 11
// speedup vs baseline: 1.7437x; 1.0616x over previous
#include <cuda_runtime.h>
#include <cstdint>

#define TSEQ  2048
#define CDIM  1024
#define NB    2
#define NHEAD 16
#define DHDIM 64
#define BTROWS (NB * TSEQ)   // 4096

typedef unsigned long long ull;

// Scratch for Q, K, V projections (flat (B*T, C) row-major == (B,H,T,Dh) view)
__device__ float g_q[NB * TSEQ * CDIM];
__device__ float g_k[NB * TSEQ * CDIM];
__device__ float g_v[NB * TSEQ * CDIM];

// ---------------- packed fp32x2 helpers (SASS FFMA2 path) -------------------
__device__ __forceinline__ ull bcast2(float x) {
    ull r; asm("mov.b64 %0, {%1, %1};" : "=l"(r) : "f"(x)); return r;
}
__device__ __forceinline__ ull pack2(float lo, float hi) {
    ull r; asm("mov.b64 %0, {%1, %2};" : "=l"(r) : "f"(lo), "f"(hi)); return r;
}
__device__ __forceinline__ float2 unpack2(ull v) {
    float2 r; asm("mov.b64 {%0, %1}, %2;" : "=f"(r.x), "=f"(r.y) : "l"(v)); return r;
}
__device__ __forceinline__ void ffma2(ull& d, ull a, ull b) {
    asm("fma.rn.f32x2 %0, %1, %2, %0;" : "+l"(d) : "l"(a), "l"(b));
}
__device__ __forceinline__ void fmul2(ull& d, ull a) {
    asm("mul.rn.f32x2 %0, %0, %1;" : "+l"(d) : "l"(a));
}

// ---------------- tf32 mma.sync helpers (plain compute_103 PTX) -------------
__device__ __forceinline__ uint32_t f2tf32(float f) {
    uint32_t u; asm("cvt.rna.tf32.f32 %0, %1;" : "=r"(u) : "f"(f)); return u;
}
__device__ __forceinline__ void split_tf32(float x, uint32_t& hi, uint32_t& lo) {
    uint32_t h = f2tf32(x);
    lo = f2tf32(x - __uint_as_float(h));
    hi = h;
}
__device__ __forceinline__ void mma_tf32(float& c0, float& c1, float& c2, float& c3,
                                         uint32_t a0, uint32_t a1, uint32_t a2, uint32_t a3,
                                         uint32_t b0, uint32_t b1) {
    asm volatile(
        "mma.sync.aligned.m16n8k8.row.col.f32.tf32.tf32.f32 "
        "{%0,%1,%2,%3}, {%4,%5,%6,%7}, {%8,%9}, {%0,%1,%2,%3};"
        : "+f"(c0), "+f"(c1), "+f"(c2), "+f"(c3)
        : "r"(a0), "r"(a1), "r"(a2), "r"(a3), "r"(b0), "r"(b1));
}

// ---------------------------------------------------------------------------
// QKV projection, 3xTF32 mma.sync: dst[m,n] = sum_k X[m,k]*W[n,k]  (x @ W^T)
// Block 128x128, BK=16 double-buffered. 8 warps in 2(m) x 4(n); warp tile
// 64x32 = 4x4 m16n8k8 fragments. C = Ah*Bh + Ah*Bl + Al*Bh (fp32-accurate).
// Smem tiles [128][20] floats (stride 20 -> (20g+t) covers all 32 banks).
// ---------------------------------------------------------------------------
#define GBK 16
#define GNK (CDIM / GBK)          // 64 stages
#define GSTRIDE 20
#define GTILE (128 * GSTRIDE)     // floats per tile-buffer
#define GSMEM_FLOATS (8 * GTILE)  // Ah,Al,Bh,Bl x 2 buffers
#define GSMEM_BYTES (GSMEM_FLOATS * 4)   // 81920

__global__ __launch_bounds__(256, 2)
void qkv_mma_kernel(const float* __restrict__ X,
                    const float* __restrict__ Wq,
                    const float* __restrict__ Wk,
                    const float* __restrict__ Wv) {
    extern __shared__ float sm[];
    float* __restrict__ sAh = sm;
    float* __restrict__ sAl = sm + 2 * GTILE;
    float* __restrict__ sBh = sm + 4 * GTILE;
    float* __restrict__ sBl = sm + 6 * GTILE;

    const float* __restrict__ W =
        (blockIdx.z == 0) ? Wq : (blockIdx.z == 1) ? Wk : Wv;
    float* __restrict__ dst =
        (blockIdx.z == 0) ? g_q : (blockIdx.z == 1) ? g_k : g_v;

    const int m0  = blockIdx.x * 128;
    const int n0  = blockIdx.y * 128;
    const int tid = threadIdx.x;
    const int wid = tid >> 5;
    const int lane = tid & 31;
    const int g = lane >> 2;          // group id (0..7)
    const int t = lane & 3;           // thread-in-group
    const int wm = (wid >> 2) * 64;   // warp m offset (0/64)
    const int wn = (wid & 3) * 32;    // warp n offset (0..96)

    const int mrow = tid >> 2;        // 0..63 (staging)
    const int kq   = (tid & 3) << 2;  // 0,4,8,12
    const float* Abase = X + (size_t)(m0 + mrow) * CDIM + kq;
    const float* Bbase = W + (size_t)(n0 + mrow) * CDIM + kq;

    float c[4][4][4];
    #pragma unroll
    for (int mi = 0; mi < 4; mi++)
        #pragma unroll
        for (int ni = 0; ni < 4; ni++)
            #pragma unroll
            for (int e = 0; e < 4; e++) c[mi][ni][e] = 0.0f;

    // stage 0
    float4 pa[2], pb[2];
    #pragma unroll
    for (int i = 0; i < 2; i++) {
        pa[i] = *(const float4*)(Abase + (size_t)(64 * i) * CDIM);
        pb[i] = *(const float4*)(Bbase + (size_t)(64 * i) * CDIM);
    }
    #pragma unroll
    for (int i = 0; i < 2; i++) {
        int adr = (mrow + 64 * i) * GSTRIDE + kq;
        uint4 h, l;
        split_tf32(pa[i].x, h.x, l.x); split_tf32(pa[i].y, h.y, l.y);
        split_tf32(pa[i].z, h.z, l.z); split_tf32(pa[i].w, h.w, l.w);
        *(uint4*)&sAh[adr] = h; *(uint4*)&sAl[adr] = l;
        split_tf32(pb[i].x, h.x, l.x); split_tf32(pb[i].y, h.y, l.y);
        split_tf32(pb[i].z, h.z, l.z); split_tf32(pb[i].w, h.w, l.w);
        *(uint4*)&sBh[adr] = h; *(uint4*)&sBl[adr] = l;
    }
    __syncthreads();

    for (int s = 0; s < GNK; s++) {
        const int buf = s & 1;
        const bool more = (s + 1 < GNK);
        if (more) {
            const int k0 = (s + 1) * GBK;
            #pragma unroll
            for (int i = 0; i < 2; i++) {
                pa[i] = *(const float4*)(Abase + (size_t)(64 * i) * CDIM + k0);
                pb[i] = *(const float4*)(Bbase + (size_t)(64 * i) * CDIM + k0);
            }
        }

        const float* Ah = sAh + buf * GTILE;
        const float* Al = sAl + buf * GTILE;
        const float* Bh = sBh + buf * GTILE;
        const float* Bl = sBl + buf * GTILE;

        #pragma unroll
        for (int ks = 0; ks < 2; ks++) {
            const int k0 = ks * 8;
            uint32_t ah[4][4], bh[4][2];
            #pragma unroll
            for (int mi = 0; mi < 4; mi++) {
                int r0 = (wm + mi * 16 + g) * GSTRIDE + k0 + t;
                ah[mi][0] = __float_as_uint(Ah[r0]);
                ah[mi][1] = __float_as_uint(Ah[r0 + 8 * GSTRIDE]);
                ah[mi][2] = __float_as_uint(Ah[r0 + 4]);
                ah[mi][3] = __float_as_uint(Ah[r0 + 8 * GSTRIDE + 4]);
            }
            #pragma unroll
            for (int ni = 0; ni < 4; ni++) {
                int b0 = (wn + ni * 8 + g) * GSTRIDE + k0 + t;
                bh[ni][0] = __float_as_uint(Bh[b0]);
                bh[ni][1] = __float_as_uint(Bh[b0 + 4]);
            }
            #pragma unroll
            for (int mi = 0; mi < 4; mi++)
                #pragma unroll
                for (int ni = 0; ni < 4; ni++)
                    mma_tf32(c[mi][ni][0], c[mi][ni][1], c[mi][ni][2], c[mi][ni][3],
                             ah[mi][0], ah[mi][1], ah[mi][2], ah[mi][3],
                             bh[ni][0], bh[ni][1]);

            uint32_t bl[4][2];
            #pragma unroll
            for (int ni = 0; ni < 4; ni++) {
                int b0 = (wn + ni * 8 + g) * GSTRIDE + k0 + t;
                bl[ni][0] = __float_as_uint(Bl[b0]);
                bl[ni][1] = __float_as_uint(Bl[b0 + 4]);
            }
            #pragma unroll
            for (int mi = 0; mi < 4; mi++)
                #pragma unroll
                for (int ni = 0; ni < 4; ni++)
                    mma_tf32(c[mi][ni][0], c[mi][ni][1], c[mi][ni][2], c[mi][ni][3],
                             ah[mi][0], ah[mi][1], ah[mi][2], ah[mi][3],
                             bl[ni][0], bl[ni][1]);

            uint32_t al[4][4];
            #pragma unroll
            for (int mi = 0; mi < 4; mi++) {
                int r0 = (wm + mi * 16 + g) * GSTRIDE + k0 + t;
                al[mi][0] = __float_as_uint(Al[r0]);
                al[mi][1] = __float_as_uint(Al[r0 + 8 * GSTRIDE]);
                al[mi][2] = __float_as_uint(Al[r0 + 4]);
                al[mi][3] = __float_as_uint(Al[r0 + 8 * GSTRIDE + 4]);
            }
            #pragma unroll
            for (int mi = 0; mi < 4; mi++)
                #pragma unroll
                for (int ni = 0; ni < 4; ni++)
                    mma_tf32(c[mi][ni][0], c[mi][ni][1], c[mi][ni][2], c[mi][ni][3],
                             al[mi][0], al[mi][1], al[mi][2], al[mi][3],
                             bh[ni][0], bh[ni][1]);
        }

        if (more) {
            const int nb = buf ^ 1;
            float* dAh = sAh + nb * GTILE; float* dAl = sAl + nb * GTILE;
            float* dBh = sBh + nb * GTILE; float* dBl = sBl + nb * GTILE;
            #pragma unroll
            for (int i = 0; i < 2; i++) {
                int adr = (mrow + 64 * i) * GSTRIDE + kq;
                uint4 h, l;
                split_tf32(pa[i].x, h.x, l.x); split_tf32(pa[i].y, h.y, l.y);
                split_tf32(pa[i].z, h.z, l.z); split_tf32(pa[i].w, h.w, l.w);
                *(uint4*)&dAh[adr] = h; *(uint4*)&dAl[adr] = l;
                split_tf32(pb[i].x, h.x, l.x); split_tf32(pb[i].y, h.y, l.y);
                split_tf32(pb[i].z, h.z, l.z); split_tf32(pb[i].w, h.w, l.w);
                *(uint4*)&dBh[adr] = h; *(uint4*)&dBl[adr] = l;
            }
            __syncthreads();
        }
    }

    #pragma unroll
    for (int mi = 0; mi < 4; mi++) {
        int r0 = m0 + wm + mi * 16 + g;
        #pragma unroll
        for (int ni = 0; ni < 4; ni++) {
            int col = n0 + wn + ni * 8 + 2 * t;
            *(float2*)(dst + (size_t)r0 * CDIM + col) =
                make_float2(c[mi][ni][0], c[mi][ni][1]);
            *(float2*)(dst + (size_t)(r0 + 8) * CDIM + col) =
                make_float2(c[mi][ni][2], c[mi][ni][3]);
        }
    }
}

// ---------------------------------------------------------------------------
// Causal flash attention, fp32, packed f32x2 (unchanged, known-good R6).
// ---------------------------------------------------------------------------
#define SQ 68
#define ATTN_SMEM_FLOATS (64 * SQ + 128 * SQ + 128 * SQ)

__global__ __launch_bounds__(256, 2)
void attn_kernel(float* __restrict__ out) {
    extern __shared__ float sm[];
    float* __restrict__ Qs  = sm;                    // [64][68]
    float* __restrict__ KsP = sm + 64 * SQ;          // K [128][68] / P [64][128]
    float* __restrict__ Vs  = KsP + 128 * SQ;        // [128][68]

    const int qi = (int)gridDim.x - 1 - (int)blockIdx.x;  // heavy tiles first
    const int bh = blockIdx.y;
    const int q0 = qi * 64;
    const size_t base = (size_t)bh * (TSEQ * DHDIM);
    const float* __restrict__ Qg = g_q + base + (size_t)q0 * DHDIM;
    const float* __restrict__ Kg = g_k + base;
    const float* __restrict__ Vg = g_v + base;
    float* __restrict__ Og = out + base + (size_t)q0 * DHDIM;

    const int tid = threadIdx.x;
    const int tx  = tid & 15;
    const int ty  = tid >> 4;

    #pragma unroll
    for (int it = 0; it < 4; it++) {
        int lin = it * 1024 + tid * 4;
        int r = lin >> 6, c = lin & 63;
        *(float4*)&Qs[r * SQ + c] = *(const float4*)(Qg + lin);
    }

    ull oacc[4][2];
    float mrow[4], lrow[4];
    #pragma unroll
    for (int i = 0; i < 4; i++) {
        oacc[i][0] = 0ull; oacc[i][1] = 0ull;
        mrow[i] = -1e30f;  lrow[i] = 0.0f;
    }

    const float SCL = 0.125f * 1.4426950408889634f;
    const int nt = (q0 + 63) / 128 + 1;

    for (int j = 0; j < nt; j++) {
        __syncthreads();
        {
            const float* Kt = Kg + (size_t)j * 128 * DHDIM;
            const float* Vt = Vg + (size_t)j * 128 * DHDIM;
            #pragma unroll
            for (int it = 0; it < 8; it++) {
                int lin = it * 1024 + tid * 4;
                int r = lin >> 6, c = lin & 63;
                *(float4*)&KsP[r * SQ + c] = *(const float4*)(Kt + lin);
                *(float4*)&Vs[r * SQ + c]  = *(const float4*)(Vt + lin);
            }
        }
        __syncthreads();

        ull s2[4][4];
        #pragma unroll
        for (int i = 0; i < 4; i++)
            #pragma unroll
            for (int p = 0; p < 4; p++) s2[i][p] = 0ull;

        #pragma unroll 2
        for (int d4 = 0; d4 < DHDIM; d4 += 4) {
            float4 q4[4], ka[4], kb[4];
            #pragma unroll
            for (int i = 0; i < 4; i++)
                q4[i] = *(const float4*)&Qs[(ty + 16 * i) * SQ + d4];
            #pragma unroll
            for (int p = 0; p < 4; p++) {
                ka[p] = *(const float4*)&KsP[(tx + 32 * p) * SQ + d4];
                kb[p] = *(const float4*)&KsP[(tx + 32 * p + 16) * SQ + d4];
            }
            #pragma unroll
            for (int e = 0; e < 4; e++) {
                ull bp[4];
                #pragma unroll
                for (int p = 0; p < 4; p++)
                    bp[p] = pack2(((const float*)&ka[p])[e],
                                  ((const float*)&kb[p])[e]);
                #pragma unroll
                for (int i = 0; i < 4; i++) {
                    ull a2 = bcast2(((const float*)&q4[i])[e]);
                    ffma2(s2[i][0], a2, bp[0]);
                    ffma2(s2[i][1], a2, bp[1]);
                    ffma2(s2[i][2], a2, bp[2]);
                    ffma2(s2[i][3], a2, bp[3]);
                }
            }
        }

        float s[4][8];
        #pragma unroll
        for (int i = 0; i < 4; i++)
            #pragma unroll
            for (int p = 0; p < 4; p++) {
                float2 u = unpack2(s2[i][p]);
                s[i][2 * p]     = u.x;
                s[i][2 * p + 1] = u.y;
            }

        const bool full = (j * 128 + 127 <= q0);
        #pragma unroll
        for (int i = 0; i < 4; i++) {
            int rg = q0 + ty + 16 * i;
            #pragma unroll
            for (int jj = 0; jj < 8; jj++) {
                float v = s[i][jj] * SCL;
                if (!full) {
                    int col = j * 128 + tx + 16 * jj;
                    if (col > rg) v = -1e30f;
                }
                s[i][jj] = v;
            }
        }

        #pragma unroll
        for (int i = 0; i < 4; i++) {
            float mloc = fmaxf(fmaxf(fmaxf(s[i][0], s[i][1]), fmaxf(s[i][2], s[i][3])),
                               fmaxf(fmaxf(s[i][4], s[i][5]), fmaxf(s[i][6], s[i][7])));
            #pragma unroll
            for (int off = 8; off >= 1; off >>= 1)
                mloc = fmaxf(mloc, __shfl_xor_sync(0xffffffffu, mloc, off));
            float mnew  = fmaxf(mrow[i], mloc);
            float alpha = exp2f(mrow[i] - mnew);
            mrow[i] = mnew;
            float rs = 0.0f;
            #pragma unroll
            for (int jj = 0; jj < 8; jj++) {
                float p = exp2f(s[i][jj] - mnew);
                s[i][jj] = p;
                rs += p;
            }
            #pragma unroll
            for (int off = 8; off >= 1; off >>= 1)
                rs += __shfl_xor_sync(0xffffffffu, rs, off);
            lrow[i] = lrow[i] * alpha + rs;
            ull al2 = bcast2(alpha);
            fmul2(oacc[i][0], al2);
            fmul2(oacc[i][1], al2);
        }

        __syncthreads();
        #pragma unroll
        for (int i = 0; i < 4; i++)
            #pragma unroll
            for (int jj = 0; jj < 8; jj++)
                KsP[(ty + 16 * i) * 128 + tx + 16 * jj] = s[i][jj];
        __syncthreads();

        #pragma unroll 4
        for (int col = 0; col < 128; col++) {
            ull v0 = *(const ull*)&Vs[col * SQ + 2 * tx];
            ull v1 = *(const ull*)&Vs[col * SQ + 2 * tx + 32];
            #pragma unroll
            for (int i = 0; i < 4; i++) {
                ull p2 = bcast2(KsP[(ty + 16 * i) * 128 + col]);
                ffma2(oacc[i][0], p2, v0);
                ffma2(oacc[i][1], p2, v1);
            }
        }
    }

    #pragma unroll
    for (int i = 0; i < 4; i++) {
        float inv = 1.0f / lrow[i];
        float2 u0 = unpack2(oacc[i][0]);
        float2 u1 = unpack2(oacc[i][1]);
        int r = ty + 16 * i;
        *(float2*)&Og[r * DHDIM + 2 * tx]      = make_float2(u0.x * inv, u0.y * inv);
        *(float2*)&Og[r * DHDIM + 2 * tx + 32] = make_float2(u1.x * inv, u1.y * inv);
    }
}

// ---------------------------------------------------------------------------
extern "C" void kernel_launch(void* const* d_in, const int* in_sizes, int n_in,
                              void* d_out, int out_size) {
    const float* x  = (const float*)d_in[0];
    const float* Wq = (const float*)d_in[1];
    const float* Wk = (const float*)d_in[2];
    const float* Wv = (const float*)d_in[3];
    float* out = (float*)d_out;

    static bool attr_done = false;
    if (!attr_done) {
        cudaFuncSetAttribute(attn_kernel,
                             cudaFuncAttributeMaxDynamicSharedMemorySize,
                             ATTN_SMEM_FLOATS * (int)sizeof(float));
        cudaFuncSetAttribute(qkv_mma_kernel,
                             cudaFuncAttributeMaxDynamicSharedMemorySize,
                             GSMEM_BYTES);
        attr_done = true;
    }

    dim3 ggrid(BTROWS / 128, CDIM / 128, 3);   // 32 x 8 x 3
    qkv_mma_kernel<<<ggrid, 256, GSMEM_BYTES>>>(x, Wq, Wk, Wv);

    dim3 agrid(TSEQ / 64, NB * NHEAD);         // 32 x 32
    attn_kernel<<<agrid, 256, ATTN_SMEM_FLOATS * (int)sizeof(float)>>>(out);

    (void)in_sizes; (void)n_in; (void)out_size;
}